// round 13
// baseline (speedup 1.0000x reference)
#include <cuda_runtime.h>
#include <cuda_bf16.h>
#include <cstdint>
#include <math.h>

#define BB   256
#define TT   128
#define EE   100
#define HH   100
#define CC   255
#define MLPD 300
#define MROWS 32768        // B*T
#define NCG  800           // gin cols (exact)
#define NCS  900           // S cols (exact)
#define KPAD 256           // padded K storage for h2 (200 real, GEMM uses 224)
#define KPX  128           // padded K for embeddings (100 real)

typedef unsigned long long ULL;

__device__ __forceinline__ void ffma2(ULL& acc, ULL a, ULL b) {
    asm volatile("fma.rn.f32x2 %0, %1, %2, %0;" : "+l"(acc) : "l"(a), "l"(b));
}
__device__ __forceinline__ ULL pack2(float x, float y) {
    ULL r; asm("mov.b64 %0, {%1,%2};" : "=l"(r) : "f"(x), "f"(y)); return r;
}
__device__ __forceinline__ float2 unpack2(ULL v) {
    float2 r; asm("mov.b64 {%0,%1}, %2;" : "=f"(r.x), "=f"(r.y) : "l"(v)); return r;
}
__device__ __forceinline__ float tanhf_fast(float x) {
    float r; asm("tanh.approx.f32 %0, %1;" : "=f"(r) : "f"(x)); return r;
}
__device__ __forceinline__ float sigf(float x) { return 0.5f * tanhf_fast(0.5f * x) + 0.5f; }
__device__ __forceinline__ void cp16s(unsigned int dst, const void* src) {
    asm volatile("cp.async.cg.shared.global [%0], [%1], 16;" :: "r"(dst), "l"(src));
}
__device__ __forceinline__ unsigned int smem_u32(const void* p) {
    return (unsigned int)__cvta_generic_to_shared(p);
}
__device__ __forceinline__ void ldm_x4(unsigned int& r0, unsigned int& r1,
                                       unsigned int& r2, unsigned int& r3,
                                       unsigned int addr) {
    asm volatile("ldmatrix.sync.aligned.m8n8.x4.shared.b16 {%0,%1,%2,%3}, [%4];"
                 : "=r"(r0), "=r"(r1), "=r"(r2), "=r"(r3) : "r"(addr));
}
__device__ __forceinline__ void mma16816(float* d, const unsigned int* a,
                                         const unsigned int* b) {
    asm volatile(
        "mma.sync.aligned.m16n8k16.row.col.f32.bf16.bf16.f32 "
        "{%0,%1,%2,%3}, {%4,%5,%6,%7}, {%8,%9}, {%0,%1,%2,%3};"
        : "+f"(d[0]), "+f"(d[1]), "+f"(d[2]), "+f"(d[3])
        : "r"(a[0]), "r"(a[1]), "r"(a[2]), "r"(a[3]), "r"(b[0]), "r"(b[1]));
}

// ---------------- device-global scratch ----------------------------------------
__device__ float d_bsum[NCG];
__device__ __nv_bfloat16 d_Xhi[(long)MROWS * KPX];    // embeddings [r=t*256+b][k]
__device__ __nv_bfloat16 d_Xlo[(long)MROWS * KPX];
__device__ __nv_bfloat16 d_Ghi[NCG * KPX];            // Wih [col][k]
__device__ __nv_bfloat16 d_Glo[NCG * KPX];
__device__ float d_gin[(long)MROWS * NCG];            // [r=t*256+b][col]
__device__ __nv_bfloat16 d_Ahi[(long)MROWS * KPAD];   // h2 [r=b*128+t][k]
__device__ __nv_bfloat16 d_Alo[(long)MROWS * KPAD];
__device__ __nv_bfloat16 d_Bhi[NCS * KPAD];           // W1 [col][k]
__device__ __nv_bfloat16 d_Blo[NCS * KPAD];
__device__ float d_S[(long)MROWS * NCS];              // [r=b*128+t][col]

// ---------------- prep ----------------------------------------------------------
__global__ void prep_k(const float* __restrict__ Wih_f, const float* __restrict__ Wih_b,
                       const float* __restrict__ bih_f, const float* __restrict__ bhh_f,
                       const float* __restrict__ bih_b, const float* __restrict__ bhh_b,
                       const float* __restrict__ W1) {
    int stride = gridDim.x * blockDim.x;
    int i0 = blockIdx.x * blockDim.x + threadIdx.x;
    for (int idx = i0; idx < NCG; idx += stride) {
        d_bsum[idx] = (idx < 400) ? (bih_f[idx] + bhh_f[idx])
                                  : (bih_b[idx - 400] + bhh_b[idx - 400]);
    }
    for (int idx = i0; idx < NCG * KPX; idx += stride) {
        int col = idx / KPX, k = idx % KPX;
        float v = 0.0f;
        if (k < 100)
            v = (col < 400) ? Wih_f[col * 100 + k] : Wih_b[(col - 400) * 100 + k];
        __nv_bfloat16 hi = __float2bfloat16(v);
        d_Ghi[idx] = hi;
        d_Glo[idx] = __float2bfloat16(v - __bfloat162float(hi));
    }
    for (int idx = i0; idx < NCS * KPAD; idx += stride) {
        int col = idx / KPAD, k = idx % KPAD;
        float v = 0.0f;
        if (k < 200) {
            int s = col / MLPD, m = col % MLPD;
            v = W1[(s * 200 + k) * MLPD + m];
        }
        __nv_bfloat16 hi = __float2bfloat16(v);
        d_Bhi[idx] = hi;
        d_Blo[idx] = __float2bfloat16(v - __bfloat162float(hi));
    }
    for (int idx = i0; idx < MROWS * (KPAD - 200); idx += stride) {
        int r = idx / (KPAD - 200), k = 200 + idx % (KPAD - 200);
        d_Ahi[(long)r * KPAD + k] = __float2bfloat16(0.0f);
        d_Alo[(long)r * KPAD + k] = __float2bfloat16(0.0f);
    }
}

// ---------------- embed gather -> bf16 hi/lo ------------------------------------
__global__ __launch_bounds__(512) void xet_k(const int* __restrict__ x,
                                             const float* __restrict__ emb) {
    __shared__ int toks[128];
    const int tid = threadIdx.x;
    const int r0 = blockIdx.x * 128;
    if (tid < 128) {
        int r = r0 + tid;
        toks[tid] = x[(r & 255) * TT + (r >> 8)];   // r = t*256+b
    }
    __syncthreads();
    for (int idx = tid; idx < 128 * KPX; idx += 512) {
        int row = idx >> 7, k = idx & 127;
        float v = (k < 100) ? emb[(long)toks[row] * EE + k] : 0.0f;
        __nv_bfloat16 hi = __float2bfloat16(v);
        long o = (long)(r0 + row) * KPX + k;
        d_Xhi[o] = hi;
        d_Xlo[o] = __float2bfloat16(v - __bfloat162float(hi));
    }
}

// ---------------- HMMA split-bf16 GEMM template ----------------------------------
#define STC_SMEM (2 * 4 * 128 * 80)
template <int KT, int KS, bool BIAS>
__device__ __forceinline__ void tc_gemm(const __nv_bfloat16* __restrict__ Ahi,
                                        const __nv_bfloat16* __restrict__ Alo,
                                        const __nv_bfloat16* __restrict__ Bhi,
                                        const __nv_bfloat16* __restrict__ Blo,
                                        float* __restrict__ C, int NC,
                                        const float* __restrict__ bias) {
    extern __shared__ char smx[];
    const unsigned int tile = smem_u32(smx);
    const int tid = threadIdx.x;
    const int wid = tid >> 5;
    const int lane = tid & 31;
    const int wr = wid >> 1;
    const int wc = wid & 1;
    const int r0 = blockIdx.x * 128;
    const int cb = min((int)blockIdx.y * 128, NC - 128);

    float acc[2][8][4];
#pragma unroll
    for (int mt = 0; mt < 2; mt++)
#pragma unroll
        for (int nt = 0; nt < 8; nt++)
#pragma unroll
            for (int j = 0; j < 4; j++) acc[mt][nt][j] = 0.0f;

#define FILL_TILE(KC, BUF) do { \
    for (int u = tid; u < 2048; u += 256) { \
        int arr = u >> 9; \
        int rem = u & 511; \
        int row = rem >> 2; \
        int c4 = rem & 3; \
        const __nv_bfloat16* src; \
        if (arr == 0)      src = &Ahi[(long)(r0 + row) * KS + (KC) + c4 * 8]; \
        else if (arr == 1) src = &Alo[(long)(r0 + row) * KS + (KC) + c4 * 8]; \
        else if (arr == 2) src = &Bhi[(long)(cb + row) * KS + (KC) + c4 * 8]; \
        else               src = &Blo[(long)(cb + row) * KS + (KC) + c4 * 8]; \
        cp16s(tile + (BUF) * 40960 + arr * 10240 + row * 80 + c4 * 16, src); \
    } \
    asm volatile("cp.async.commit_group;"); \
} while (0)

    FILL_TILE(0, 0);

    for (int kt = 0; kt < KT; kt++) {
        const int p = kt & 1;
        if (kt + 1 < KT) {
            FILL_TILE((kt + 1) * 32, p ^ 1);
            asm volatile("cp.async.wait_group 1;");
        } else {
            asm volatile("cp.async.wait_group 0;");
        }
        __syncthreads();

        const unsigned int bufb = tile + p * 40960;
        const unsigned int Ahib = bufb;
        const unsigned int Alob = bufb + 10240;
        const unsigned int Bhib = bufb + 20480;
        const unsigned int Blob = bufb + 30720;

#pragma unroll
        for (int ks = 0; ks < 2; ks++) {
            unsigned int ahi[2][4], alo[2][4];
#pragma unroll
            for (int mt = 0; mt < 2; mt++) {
                int row = wr * 32 + mt * 16 + (lane & 15);
                unsigned int koff = ((lane >> 4) * 8 + ks * 16) * 2;
                ldm_x4(ahi[mt][0], ahi[mt][1], ahi[mt][2], ahi[mt][3],
                       Ahib + row * 80 + koff);
                ldm_x4(alo[mt][0], alo[mt][1], alo[mt][2], alo[mt][3],
                       Alob + row * 80 + koff);
            }
#pragma unroll
            for (int jn = 0; jn < 4; jn++) {
                int nrow = wc * 64 + jn * 16 + ((lane >> 4) * 8) + (lane & 7);
                unsigned int koff = (ks * 16 + ((lane >> 3) & 1) * 8) * 2;
                unsigned int bhi[4], blo[4];
                ldm_x4(bhi[0], bhi[1], bhi[2], bhi[3], Bhib + nrow * 80 + koff);
                ldm_x4(blo[0], blo[1], blo[2], blo[3], Blob + nrow * 80 + koff);
#pragma unroll
                for (int half = 0; half < 2; half++) {
                    int nt = jn * 2 + half;
#pragma unroll
                    for (int mt = 0; mt < 2; mt++) {
                        mma16816(acc[mt][nt], ahi[mt], bhi + half * 2);
                        mma16816(acc[mt][nt], ahi[mt], blo + half * 2);
                        mma16816(acc[mt][nt], alo[mt], bhi + half * 2);
                    }
                }
            }
        }
        __syncthreads();
    }

#pragma unroll
    for (int mt = 0; mt < 2; mt++)
#pragma unroll
        for (int nt = 0; nt < 8; nt++) {
            int rg = r0 + wr * 32 + mt * 16 + (lane >> 2);
            int cg = cb + wc * 64 + nt * 8 + (lane & 3) * 2;
            float b0 = 0.f, b1 = 0.f;
            if (BIAS) { float2 bv = *(const float2*)&bias[cg]; b0 = bv.x; b1 = bv.y; }
            *(float2*)&C[(long)rg * NC + cg] =
                make_float2(acc[mt][nt][0] + b0, acc[mt][nt][1] + b1);
            *(float2*)&C[(long)(rg + 8) * NC + cg] =
                make_float2(acc[mt][nt][2] + b0, acc[mt][nt][3] + b1);
        }
#undef FILL_TILE
}

__global__ __launch_bounds__(256, 2) void gates_tc_k() {
    tc_gemm<4, KPX, true>(d_Xhi, d_Xlo, d_Ghi, d_Glo, d_gin, NCG, d_bsum);
}
__global__ __launch_bounds__(256, 2) void s_tc_k() {
    tc_gemm<7, KPAD, false>(d_Ahi, d_Alo, d_Bhi, d_Blo, d_S, NCS, nullptr);
}

// ---------------- LSTM recurrence: pointer-induction, unroll-2 -------------------
// 128 blocks: dir = blk>>6, batch base = (blk&63)*4, 800 threads,
// tid = hid*8 + q*2 + gh (q = k-quarter AND batch owner, gh = gate pair).
__global__ __launch_bounds__(800, 1) void lstm_k(const float* __restrict__ Whh_f,
                                                 const float* __restrict__ Whh_b) {
    __shared__ __align__(16) float hs0[4 * 116];
    __shared__ __align__(16) float hs1[4 * 116];
    const int tid = threadIdx.x;
    const int dir = blockIdx.x >> 6;
    const int b0 = (blockIdx.x & 63) * 4;
    const float* __restrict__ Whh = dir ? Whh_b : Whh_f;

    const int hid = tid >> 3;
    const int sub = tid & 7;
    const int q = sub >> 1;
    const int gh = sub & 1;
    const int hi2 = (q >> 1) & 1;
    const int lo = q & 1;

    ULL w[2][13];
#pragma unroll
    for (int g2 = 0; g2 < 2; g2++) {
        const float* row = Whh + ((gh * 2 + g2) * 100 + hid) * 100 + q * 25;
#pragma unroll
        for (int p = 0; p < 12; p++) w[g2][p] = pack2(row[2 * p], row[2 * p + 1]);
        w[g2][12] = pack2(row[24], 0.0f);
    }
    for (int idx = tid; idx < 4 * 116; idx += 800) { hs0[idx] = 0.0f; }

    // hoisted pointers / strides
    const int t0 = dir ? (TT - 1) : 0;
    const long gstride = dir ? -(long)(256 * NCG) : (long)(256 * NCG);
    const float* gp = &d_gin[(long)(t0 * 256 + b0 + q) * NCG + dir * 400 + gh * 200 + hid];
    const long astride = dir ? -(long)KPAD : (long)KPAD;
    __nv_bfloat16* aph = &d_Ahi[((long)(b0 + q) * TT + t0) * KPAD + dir * 100 + hid];
    __nv_bfloat16* apl = &d_Alo[((long)(b0 + q) * TT + t0) * KPAD + dir * 100 + hid];
    const int hslot = q * 116 + (hid / 25) * 28 + (hid % 25);
    const int q28 = q * 28;

    float c = 0.0f;
    float g0 = gp[0], g1 = gp[100];
    __syncthreads();

#define LSTM_STEP(HBUF, HNXT, LAST) do { \
    float v[4][2]; \
    _Pragma("unroll") \
    for (int b = 0; b < 4; b++) { \
        const float* hb = &(HBUF)[b * 116 + q28]; \
        ULL a0 = 0ull, a1 = 0ull; \
        _Pragma("unroll") \
        for (int m = 0; m < 6; m++) { \
            ulonglong2 hp = *(const ulonglong2*)(hb + 4 * m); \
            ffma2(a0, w[0][2 * m], hp.x); ffma2(a0, w[0][2 * m + 1], hp.y); \
            ffma2(a1, w[1][2 * m], hp.x); ffma2(a1, w[1][2 * m + 1], hp.y); \
        } \
        { \
            ULL ht = *(const ULL*)(hb + 24); \
            ffma2(a0, w[0][12], ht); ffma2(a1, w[1][12], ht); \
        } \
        float2 f0 = unpack2(a0), f1 = unpack2(a1); \
        v[b][0] = f0.x + f0.y; \
        v[b][1] = f1.x + f1.y; \
    } \
    float u[2][2]; \
    _Pragma("unroll") \
    for (int j = 0; j < 2; j++) \
        _Pragma("unroll") \
        for (int g = 0; g < 2; g++) { \
            float keep = hi2 ? v[2 + j][g] : v[j][g]; \
            float send = hi2 ? v[j][g]     : v[2 + j][g]; \
            u[j][g] = keep + __shfl_xor_sync(0xFFFFFFFFu, send, 4); \
        } \
    float s0, s1; \
    { \
        float k0 = lo ? u[1][0] : u[0][0]; \
        float e0 = lo ? u[0][0] : u[1][0]; \
        s0 = k0 + __shfl_xor_sync(0xFFFFFFFFu, e0, 2); \
        float k1 = lo ? u[1][1] : u[0][1]; \
        float e1 = lo ? u[0][1] : u[1][1]; \
        s1 = k1 + __shfl_xor_sync(0xFFFFFFFFu, e1, 2); \
    } \
    float uA = g0 + s0; \
    float uB = g1 + s1; \
    float oA = __shfl_xor_sync(0xFFFFFFFFu, uA, 1); \
    float oB = __shfl_xor_sync(0xFFFFFFFFu, uB, 1); \
    float pi = gh ? oA : uA; \
    float pf = gh ? oB : uB; \
    float pg = gh ? uA : oA; \
    float po = gh ? uB : oB; \
    c = sigf(pf) * c + sigf(pi) * tanhf_fast(pg); \
    float h = sigf(po) * tanhf_fast(c); \
    if (gh == 0) { \
        (HNXT)[hslot] = h; \
        __nv_bfloat16 bh = __float2bfloat16(h); \
        *aph = bh; \
        *apl = __float2bfloat16(h - __bfloat162float(bh)); \
    } \
    if (!(LAST)) { \
        aph += astride; apl += astride; \
        gp += gstride; \
        g0 = gp[0]; g1 = gp[100]; \
    } \
    __syncthreads(); \
} while (0)

    for (int sp = 0; sp < TT / 2 - 1; sp++) {
        LSTM_STEP(hs0, hs1, false);
        LSTM_STEP(hs1, hs0, false);
    }
    LSTM_STEP(hs0, hs1, false);
    LSTM_STEP(hs1, hs0, true);
#undef LSTM_STEP
}

// ---------------- combine: gather + tanh + (300->3) + softmax --------------------
__global__ __launch_bounds__(256) void combine_k(const int* __restrict__ paths,
                                                 const float* __restrict__ b1,
                                                 const float* __restrict__ W2,
                                                 const float* __restrict__ b2,
                                                 float* __restrict__ out) {
    const int warp = (blockIdx.x * blockDim.x + threadIdx.x) >> 5;
    const int lane = threadIdx.x & 31;
    if (warp >= BB * CC) return;
    const int b = warp / CC;

    const int* p = &paths[warp * 3];
    int p0 = __ldg(p), p1 = __ldg(p + 1), p2 = __ldg(p + 2);
    int i0 = min(max(p0, 0), TT - 1);
    int i1 = min(max(p1, 0), TT - 1);
    int i2 = min(max(p2, 0), TT - 1);

    const float* S0 = &d_S[(long)(b * TT + i0) * NCS];
    const float* S1 = &d_S[(long)(b * TT + i1) * NCS + 300];
    const float* S2 = &d_S[(long)(b * TT + i2) * NCS + 600];

    float z0 = 0.f, z1 = 0.f, z2 = 0.f;
    for (int m = lane; m < MLPD; m += 32) {
        float hv = __ldg(&b1[m]);
        if (p0 >= 0) hv += S0[m];
        if (p1 >= 0) hv += S1[m];
        if (p2 >= 0) hv += S2[m];
        hv = tanhf_fast(hv);
        z0 = fmaf(hv, __ldg(&W2[m * 3 + 0]), z0);
        z1 = fmaf(hv, __ldg(&W2[m * 3 + 1]), z1);
        z2 = fmaf(hv, __ldg(&W2[m * 3 + 2]), z2);
    }
#pragma unroll
    for (int off = 16; off; off >>= 1) {
        z0 += __shfl_xor_sync(0xFFFFFFFFu, z0, off);
        z1 += __shfl_xor_sync(0xFFFFFFFFu, z1, off);
        z2 += __shfl_xor_sync(0xFFFFFFFFu, z2, off);
    }
    if (lane == 0) {
        z0 += __ldg(&b2[0]); z1 += __ldg(&b2[1]); z2 += __ldg(&b2[2]);
        float mx = fmaxf(z0, fmaxf(z1, z2));
        float e0 = __expf(z0 - mx), e1 = __expf(z1 - mx), e2 = __expf(z2 - mx);
        float inv = 1.0f / (e0 + e1 + e2);
        out[warp * 3 + 0] = e0 * inv;
        out[warp * 3 + 1] = e1 * inv;
        out[warp * 3 + 2] = e2 * inv;
    }
}

// -------------------------------- launch -----------------------------------------
extern "C" void kernel_launch(void* const* d_in, const int* in_sizes, int n_in,
                              void* d_out, int out_size) {
    const int*   x     = (const int*)  d_in[0];
    const int*   paths = (const int*)  d_in[1];
    const float* emb   = (const float*)d_in[2];
    const float* Whh_f = (const float*)d_in[4];
    const float* Whh_b = (const float*)d_in[8];
    const float* W1    = (const float*)d_in[11];
    const float* b1    = (const float*)d_in[12];
    const float* W2    = (const float*)d_in[13];
    const float* b2    = (const float*)d_in[14];
    float* out = (float*)d_out;

    cudaFuncSetAttribute(gates_tc_k, cudaFuncAttributeMaxDynamicSharedMemorySize, STC_SMEM);
    cudaFuncSetAttribute(s_tc_k, cudaFuncAttributeMaxDynamicSharedMemorySize, STC_SMEM);

    prep_k<<<256, 256>>>((const float*)d_in[3], (const float*)d_in[7],
                         (const float*)d_in[5], (const float*)d_in[6],
                         (const float*)d_in[9], (const float*)d_in[10], W1);

    xet_k<<<256, 512>>>(x, emb);

    { dim3 g(256, 7); gates_tc_k<<<g, 256, STC_SMEM>>>(); }   // HMMA gates GEMM

    lstm_k<<<128, 800>>>(Whh_f, Whh_b);

    { dim3 g(256, 8); s_tc_k<<<g, 256, STC_SMEM>>>(); }       // HMMA S GEMM

    {
        int warps = BB * CC;
        int blocks = (warps * 32 + 255) / 256;
        combine_k<<<blocks, 256>>>(paths, b1, W2, b2, out);
    }
}

// round 14
// speedup vs baseline: 1.0464x; 1.0464x over previous
#include <cuda_runtime.h>
#include <cuda_bf16.h>
#include <cstdint>
#include <math.h>

#define BB   256
#define TT   128
#define EE   100
#define HH   100
#define CC   255
#define MLPD 300
#define MROWS 32768        // B*T
#define NCG  800           // gin cols (exact)
#define NCS  900           // S cols (exact)
#define KPAD 256           // padded K storage for h2 (200 real, GEMM uses 224)
#define KPX  128           // padded K for embeddings (100 real)

typedef unsigned long long ULL;

__device__ __forceinline__ void ffma2(ULL& acc, ULL a, ULL b) {
    asm volatile("fma.rn.f32x2 %0, %1, %2, %0;" : "+l"(acc) : "l"(a), "l"(b));
}
__device__ __forceinline__ ULL pack2(float x, float y) {
    ULL r; asm("mov.b64 %0, {%1,%2};" : "=l"(r) : "f"(x), "f"(y)); return r;
}
__device__ __forceinline__ float2 unpack2(ULL v) {
    float2 r; asm("mov.b64 {%0,%1}, %2;" : "=f"(r.x), "=f"(r.y) : "l"(v)); return r;
}
__device__ __forceinline__ float tanhf_fast(float x) {
    float r; asm("tanh.approx.f32 %0, %1;" : "=f"(r) : "f"(x)); return r;
}
__device__ __forceinline__ float sigf(float x) { return 0.5f * tanhf_fast(0.5f * x) + 0.5f; }
__device__ __forceinline__ void cp16s(unsigned int dst, const void* src) {
    asm volatile("cp.async.cg.shared.global [%0], [%1], 16;" :: "r"(dst), "l"(src));
}
__device__ __forceinline__ unsigned int smem_u32(const void* p) {
    return (unsigned int)__cvta_generic_to_shared(p);
}
__device__ __forceinline__ void ldm_x4(unsigned int& r0, unsigned int& r1,
                                       unsigned int& r2, unsigned int& r3,
                                       unsigned int addr) {
    asm volatile("ldmatrix.sync.aligned.m8n8.x4.shared.b16 {%0,%1,%2,%3}, [%4];"
                 : "=r"(r0), "=r"(r1), "=r"(r2), "=r"(r3) : "r"(addr));
}
__device__ __forceinline__ void mma16816(float* d, const unsigned int* a,
                                         const unsigned int* b) {
    asm volatile(
        "mma.sync.aligned.m16n8k16.row.col.f32.bf16.bf16.f32 "
        "{%0,%1,%2,%3}, {%4,%5,%6,%7}, {%8,%9}, {%0,%1,%2,%3};"
        : "+f"(d[0]), "+f"(d[1]), "+f"(d[2]), "+f"(d[3])
        : "r"(a[0]), "r"(a[1]), "r"(a[2]), "r"(a[3]), "r"(b[0]), "r"(b[1]));
}

// ---------------- device-global scratch ----------------------------------------
__device__ float d_bsum[NCG];
__device__ __nv_bfloat16 d_Xhi[(long)MROWS * KPX];    // embeddings [r=t*256+b][k]
__device__ __nv_bfloat16 d_Xlo[(long)MROWS * KPX];
__device__ __nv_bfloat16 d_Ghi[NCG * KPX];            // Wih [col][k]
__device__ __nv_bfloat16 d_Glo[NCG * KPX];
__device__ float d_gin[(long)MROWS * NCG];            // [r=t*256+b][col]
__device__ __nv_bfloat16 d_Ahi[(long)MROWS * KPAD];   // h2 [r=b*128+t][k]
__device__ __nv_bfloat16 d_Alo[(long)MROWS * KPAD];
__device__ __nv_bfloat16 d_Bhi[NCS * KPAD];           // W1 [col][k]
__device__ __nv_bfloat16 d_Blo[NCS * KPAD];
__device__ float d_S[(long)MROWS * NCS];              // [r=b*128+t][col]

// ---------------- prep ----------------------------------------------------------
__global__ void prep_k(const float* __restrict__ Wih_f, const float* __restrict__ Wih_b,
                       const float* __restrict__ bih_f, const float* __restrict__ bhh_f,
                       const float* __restrict__ bih_b, const float* __restrict__ bhh_b,
                       const float* __restrict__ W1) {
    int stride = gridDim.x * blockDim.x;
    int i0 = blockIdx.x * blockDim.x + threadIdx.x;
    for (int idx = i0; idx < NCG; idx += stride) {
        d_bsum[idx] = (idx < 400) ? (bih_f[idx] + bhh_f[idx])
                                  : (bih_b[idx - 400] + bhh_b[idx - 400]);
    }
    for (int idx = i0; idx < NCG * KPX; idx += stride) {
        int col = idx / KPX, k = idx % KPX;
        float v = 0.0f;
        if (k < 100)
            v = (col < 400) ? Wih_f[col * 100 + k] : Wih_b[(col - 400) * 100 + k];
        __nv_bfloat16 hi = __float2bfloat16(v);
        d_Ghi[idx] = hi;
        d_Glo[idx] = __float2bfloat16(v - __bfloat162float(hi));
    }
    for (int idx = i0; idx < NCS * KPAD; idx += stride) {
        int col = idx / KPAD, k = idx % KPAD;
        float v = 0.0f;
        if (k < 200) {
            int s = col / MLPD, m = col % MLPD;
            v = W1[(s * 200 + k) * MLPD + m];
        }
        __nv_bfloat16 hi = __float2bfloat16(v);
        d_Bhi[idx] = hi;
        d_Blo[idx] = __float2bfloat16(v - __bfloat162float(hi));
    }
    // zero only k = 200..223 (the GEMM reads K = 224 max)
    for (int idx = i0; idx < MROWS * 24; idx += stride) {
        int r = idx / 24, k = 200 + idx % 24;
        d_Ahi[(long)r * KPAD + k] = __float2bfloat16(0.0f);
        d_Alo[(long)r * KPAD + k] = __float2bfloat16(0.0f);
    }
}

// ---------------- embed gather -> bf16 hi/lo ------------------------------------
__global__ __launch_bounds__(512) void xet_k(const int* __restrict__ x,
                                             const float* __restrict__ emb) {
    __shared__ int toks[128];
    const int tid = threadIdx.x;
    const int r0 = blockIdx.x * 128;
    if (tid < 128) {
        int r = r0 + tid;
        toks[tid] = x[(r & 255) * TT + (r >> 8)];   // r = t*256+b
    }
    __syncthreads();
    for (int idx = tid; idx < 128 * KPX; idx += 512) {
        int row = idx >> 7, k = idx & 127;
        float v = (k < 100) ? emb[(long)toks[row] * EE + k] : 0.0f;
        __nv_bfloat16 hi = __float2bfloat16(v);
        long o = (long)(r0 + row) * KPX + k;
        d_Xhi[o] = hi;
        d_Xlo[o] = __float2bfloat16(v - __bfloat162float(hi));
    }
}

// ---------------- HMMA split-bf16 GEMM template ----------------------------------
#define STC_SMEM (2 * 4 * 128 * 80)
template <int KT, int KS, bool BIAS>
__device__ __forceinline__ void tc_gemm(const __nv_bfloat16* __restrict__ Ahi,
                                        const __nv_bfloat16* __restrict__ Alo,
                                        const __nv_bfloat16* __restrict__ Bhi,
                                        const __nv_bfloat16* __restrict__ Blo,
                                        float* __restrict__ C, int NC,
                                        const float* __restrict__ bias) {
    extern __shared__ char smx[];
    const unsigned int tile = smem_u32(smx);
    const int tid = threadIdx.x;
    const int wid = tid >> 5;
    const int lane = tid & 31;
    const int wr = wid >> 1;
    const int wc = wid & 1;
    const int r0 = blockIdx.x * 128;
    const int cb = min((int)blockIdx.y * 128, NC - 128);

    float acc[2][8][4];
#pragma unroll
    for (int mt = 0; mt < 2; mt++)
#pragma unroll
        for (int nt = 0; nt < 8; nt++)
#pragma unroll
            for (int j = 0; j < 4; j++) acc[mt][nt][j] = 0.0f;

#define FILL_TILE(KC, BUF) do { \
    for (int u = tid; u < 2048; u += 256) { \
        int arr = u >> 9; \
        int rem = u & 511; \
        int row = rem >> 2; \
        int c4 = rem & 3; \
        const __nv_bfloat16* src; \
        if (arr == 0)      src = &Ahi[(long)(r0 + row) * KS + (KC) + c4 * 8]; \
        else if (arr == 1) src = &Alo[(long)(r0 + row) * KS + (KC) + c4 * 8]; \
        else if (arr == 2) src = &Bhi[(long)(cb + row) * KS + (KC) + c4 * 8]; \
        else               src = &Blo[(long)(cb + row) * KS + (KC) + c4 * 8]; \
        cp16s(tile + (BUF) * 40960 + arr * 10240 + row * 80 + c4 * 16, src); \
    } \
    asm volatile("cp.async.commit_group;"); \
} while (0)

    FILL_TILE(0, 0);

    for (int kt = 0; kt < KT; kt++) {
        const int p = kt & 1;
        if (kt + 1 < KT) {
            FILL_TILE((kt + 1) * 32, p ^ 1);
            asm volatile("cp.async.wait_group 1;");
        } else {
            asm volatile("cp.async.wait_group 0;");
        }
        __syncthreads();

        const unsigned int bufb = tile + p * 40960;
        const unsigned int Ahib = bufb;
        const unsigned int Alob = bufb + 10240;
        const unsigned int Bhib = bufb + 20480;
        const unsigned int Blob = bufb + 30720;

#pragma unroll
        for (int ks = 0; ks < 2; ks++) {
            unsigned int ahi[2][4], alo[2][4];
#pragma unroll
            for (int mt = 0; mt < 2; mt++) {
                int row = wr * 32 + mt * 16 + (lane & 15);
                unsigned int koff = ((lane >> 4) * 8 + ks * 16) * 2;
                ldm_x4(ahi[mt][0], ahi[mt][1], ahi[mt][2], ahi[mt][3],
                       Ahib + row * 80 + koff);
                ldm_x4(alo[mt][0], alo[mt][1], alo[mt][2], alo[mt][3],
                       Alob + row * 80 + koff);
            }
#pragma unroll
            for (int jn = 0; jn < 4; jn++) {
                int nrow = wc * 64 + jn * 16 + ((lane >> 4) * 8) + (lane & 7);
                unsigned int koff = (ks * 16 + ((lane >> 3) & 1) * 8) * 2;
                unsigned int bhi[4], blo[4];
                ldm_x4(bhi[0], bhi[1], bhi[2], bhi[3], Bhib + nrow * 80 + koff);
                ldm_x4(blo[0], blo[1], blo[2], blo[3], Blob + nrow * 80 + koff);
#pragma unroll
                for (int half = 0; half < 2; half++) {
                    int nt = jn * 2 + half;
#pragma unroll
                    for (int mt = 0; mt < 2; mt++) {
                        mma16816(acc[mt][nt], ahi[mt], bhi + half * 2);
                        mma16816(acc[mt][nt], ahi[mt], blo + half * 2);
                        mma16816(acc[mt][nt], alo[mt], bhi + half * 2);
                    }
                }
            }
        }
        __syncthreads();
    }

#pragma unroll
    for (int mt = 0; mt < 2; mt++)
#pragma unroll
        for (int nt = 0; nt < 8; nt++) {
            int rg = r0 + wr * 32 + mt * 16 + (lane >> 2);
            int cg = cb + wc * 64 + nt * 8 + (lane & 3) * 2;
            float b0 = 0.f, b1 = 0.f;
            if (BIAS) { float2 bv = *(const float2*)&bias[cg]; b0 = bv.x; b1 = bv.y; }
            *(float2*)&C[(long)rg * NC + cg] =
                make_float2(acc[mt][nt][0] + b0, acc[mt][nt][1] + b1);
            *(float2*)&C[(long)(rg + 8) * NC + cg] =
                make_float2(acc[mt][nt][2] + b0, acc[mt][nt][3] + b1);
        }
#undef FILL_TILE
}

__global__ __launch_bounds__(256, 2) void gates_tc_k() {
    tc_gemm<4, KPX, true>(d_Xhi, d_Xlo, d_Ghi, d_Glo, d_gin, NCG, d_bsum);
}
__global__ __launch_bounds__(256, 2) void s_tc_k() {
    tc_gemm<7, KPAD, false>(d_Ahi, d_Alo, d_Bhi, d_Blo, d_S, NCS, nullptr);
}

// ---------------- LSTM recurrence (R12-proven loop; bf16 hi/lo h output) ---------
__global__ __launch_bounds__(800, 1) void lstm_k(const float* __restrict__ Whh_f,
                                                 const float* __restrict__ Whh_b) {
    __shared__ __align__(16) float hs[2][4 * 116];
    const int tid = threadIdx.x;
    const int dir = blockIdx.x >> 6;
    const int b0 = (blockIdx.x & 63) * 4;
    const float* __restrict__ Whh = dir ? Whh_b : Whh_f;

    const int hid = tid >> 3;
    const int sub = tid & 7;
    const int q = sub >> 1;
    const int gh = sub & 1;
    const int hi2 = (q >> 1) & 1;
    const int lo = q & 1;

    ULL w[2][13];
#pragma unroll
    for (int g2 = 0; g2 < 2; g2++) {
        const float* row = Whh + ((gh * 2 + g2) * 100 + hid) * 100 + q * 25;
#pragma unroll
        for (int p = 0; p < 12; p++) w[g2][p] = pack2(row[2 * p], row[2 * p + 1]);
        w[g2][12] = pack2(row[24], 0.0f);
    }
    for (int idx = tid; idx < 2 * 4 * 116; idx += 800) hs[0][idx] = 0.0f;

    const int hq = hid / 25, hr = hid % 25;
    float c = 0.0f;
    float g0, g1;
    {
        int t0 = dir ? (TT - 1) : 0;
        const float* gp = &d_gin[((long)(t0 * 256 + b0 + q)) * NCG + dir * 400 + gh * 200 + hid];
        g0 = gp[0]; g1 = gp[100];
    }
    __syncthreads();

    for (int step = 0; step < TT; ++step) {
        const int t = dir ? (TT - 1 - step) : step;
        const float* hbuf = hs[step & 1];
        float* hnxt = hs[(step + 1) & 1];

        float v[4][2];
#pragma unroll
        for (int b = 0; b < 4; b++) {
            const float* hb = &hbuf[b * 116 + q * 28];
            ULL a0 = 0ull, a1 = 0ull;
#pragma unroll
            for (int m = 0; m < 6; m++) {
                ulonglong2 hp = *(const ulonglong2*)(hb + 4 * m);
                ffma2(a0, w[0][2 * m], hp.x); ffma2(a0, w[0][2 * m + 1], hp.y);
                ffma2(a1, w[1][2 * m], hp.x); ffma2(a1, w[1][2 * m + 1], hp.y);
            }
            {
                ULL ht = *(const ULL*)(hb + 24);
                ffma2(a0, w[0][12], ht); ffma2(a1, w[1][12], ht);
            }
            float2 f0 = unpack2(a0), f1 = unpack2(a1);
            v[b][0] = f0.x + f0.y;
            v[b][1] = f1.x + f1.y;
        }

        float u[2][2];
#pragma unroll
        for (int j = 0; j < 2; j++)
#pragma unroll
            for (int g = 0; g < 2; g++) {
                float keep = hi2 ? v[2 + j][g] : v[j][g];
                float send = hi2 ? v[j][g]     : v[2 + j][g];
                u[j][g] = keep + __shfl_xor_sync(0xFFFFFFFFu, send, 4);
            }
        float s0, s1;
        {
            float k0 = lo ? u[1][0] : u[0][0];
            float e0 = lo ? u[0][0] : u[1][0];
            s0 = k0 + __shfl_xor_sync(0xFFFFFFFFu, e0, 2);
            float k1 = lo ? u[1][1] : u[0][1];
            float e1 = lo ? u[0][1] : u[1][1];
            s1 = k1 + __shfl_xor_sync(0xFFFFFFFFu, e1, 2);
        }

        float uA = g0 + s0;
        float uB = g1 + s1;
        float oA = __shfl_xor_sync(0xFFFFFFFFu, uA, 1);
        float oB = __shfl_xor_sync(0xFFFFFFFFu, uB, 1);
        float pi = gh ? oA : uA;
        float pf = gh ? oB : uB;
        float pg = gh ? uA : oA;
        float po = gh ? uB : oB;
        c = sigf(pf) * c + sigf(pi) * tanhf_fast(pg);
        float h = sigf(po) * tanhf_fast(c);
        if (gh == 0) {
            hnxt[q * 116 + hq * 28 + hr] = h;
            long r = (long)(b0 + q) * TT + t;
            __nv_bfloat16 bh = __float2bfloat16(h);
            __nv_bfloat16 bl = __float2bfloat16(h - __bfloat162float(bh));
            d_Ahi[r * KPAD + dir * 100 + hid] = bh;
            d_Alo[r * KPAD + dir * 100 + hid] = bl;
        }
        {
            int sn = (step + 1 < TT) ? (step + 1) : step;
            int tn = dir ? (TT - 1 - sn) : sn;
            const float* gp = &d_gin[((long)(tn * 256 + b0 + q)) * NCG + dir * 400 + gh * 200 + hid];
            g0 = gp[0]; g1 = gp[100];
        }
        __syncthreads();
    }
}

// ---------------- combine: smem-staged weights + gather + tanh + softmax ---------
__global__ __launch_bounds__(256) void combine_k(const int* __restrict__ paths,
                                                 const float* __restrict__ b1,
                                                 const float* __restrict__ W2,
                                                 const float* __restrict__ b2,
                                                 float* __restrict__ out) {
    __shared__ float sb1[MLPD];
    __shared__ float sW2[MLPD * 3];
    __shared__ float sb2[3];
    const int tid = threadIdx.x;
    for (int i = tid; i < MLPD; i += 256) sb1[i] = b1[i];
    for (int i = tid; i < MLPD * 3; i += 256) sW2[i] = W2[i];
    if (tid < 3) sb2[tid] = b2[tid];
    __syncthreads();

    const int warp = (blockIdx.x * blockDim.x + tid) >> 5;
    const int lane = tid & 31;
    if (warp >= BB * CC) return;
    const int b = warp / CC;

    const int* p = &paths[warp * 3];
    int p0 = __ldg(p), p1 = __ldg(p + 1), p2 = __ldg(p + 2);
    int i0 = min(max(p0, 0), TT - 1);
    int i1 = min(max(p1, 0), TT - 1);
    int i2 = min(max(p2, 0), TT - 1);

    const float* S0 = &d_S[(long)(b * TT + i0) * NCS];
    const float* S1 = &d_S[(long)(b * TT + i1) * NCS + 300];
    const float* S2 = &d_S[(long)(b * TT + i2) * NCS + 600];

    float z0 = 0.f, z1 = 0.f, z2 = 0.f;
    for (int m = lane; m < MLPD; m += 32) {
        float hv = sb1[m];
        if (p0 >= 0) hv += S0[m];
        if (p1 >= 0) hv += S1[m];
        if (p2 >= 0) hv += S2[m];
        hv = tanhf_fast(hv);
        z0 = fmaf(hv, sW2[m * 3 + 0], z0);
        z1 = fmaf(hv, sW2[m * 3 + 1], z1);
        z2 = fmaf(hv, sW2[m * 3 + 2], z2);
    }
#pragma unroll
    for (int off = 16; off; off >>= 1) {
        z0 += __shfl_xor_sync(0xFFFFFFFFu, z0, off);
        z1 += __shfl_xor_sync(0xFFFFFFFFu, z1, off);
        z2 += __shfl_xor_sync(0xFFFFFFFFu, z2, off);
    }
    if (lane == 0) {
        z0 += sb2[0]; z1 += sb2[1]; z2 += sb2[2];
        float mx = fmaxf(z0, fmaxf(z1, z2));
        float e0 = __expf(z0 - mx), e1 = __expf(z1 - mx), e2 = __expf(z2 - mx);
        float inv = 1.0f / (e0 + e1 + e2);
        out[warp * 3 + 0] = e0 * inv;
        out[warp * 3 + 1] = e1 * inv;
        out[warp * 3 + 2] = e2 * inv;
    }
}

// -------------------------------- launch -----------------------------------------
extern "C" void kernel_launch(void* const* d_in, const int* in_sizes, int n_in,
                              void* d_out, int out_size) {
    const int*   x     = (const int*)  d_in[0];
    const int*   paths = (const int*)  d_in[1];
    const float* emb   = (const float*)d_in[2];
    const float* Whh_f = (const float*)d_in[4];
    const float* Whh_b = (const float*)d_in[8];
    const float* W1    = (const float*)d_in[11];
    const float* b1    = (const float*)d_in[12];
    const float* W2    = (const float*)d_in[13];
    const float* b2    = (const float*)d_in[14];
    float* out = (float*)d_out;

    cudaFuncSetAttribute(gates_tc_k, cudaFuncAttributeMaxDynamicSharedMemorySize, STC_SMEM);
    cudaFuncSetAttribute(s_tc_k, cudaFuncAttributeMaxDynamicSharedMemorySize, STC_SMEM);

    prep_k<<<256, 256>>>((const float*)d_in[3], (const float*)d_in[7],
                         (const float*)d_in[5], (const float*)d_in[6],
                         (const float*)d_in[9], (const float*)d_in[10], W1);

    xet_k<<<256, 512>>>(x, emb);

    { dim3 g(256, 7); gates_tc_k<<<g, 256, STC_SMEM>>>(); }   // HMMA gates GEMM

    lstm_k<<<128, 800>>>(Whh_f, Whh_b);

    { dim3 g(256, 8); s_tc_k<<<g, 256, STC_SMEM>>>(); }       // HMMA S GEMM

    {
        int warps = BB * CC;
        int blocks = (warps * 32 + 255) / 256;
        combine_k<<<blocks, 256>>>(paths, b1, W2, b2, out);
    }
}

// round 15
// speedup vs baseline: 1.0636x; 1.0164x over previous
#include <cuda_runtime.h>
#include <cuda_bf16.h>
#include <cstdint>
#include <math.h>

#define BB   256
#define TT   128
#define EE   100
#define HH   100
#define CC   255
#define MLPD 300
#define MROWS 32768        // B*T
#define NCG  800           // gin cols (exact)
#define NCS  900           // S cols (exact)
#define KPAD 256           // storage stride for h2 (208 used: 200 real + 8 pad)
#define KPX  128           // storage stride for embeddings (112 used: 100 real + 12 pad)

typedef unsigned long long ULL;

__device__ __forceinline__ ULL pack2(float x, float y) {
    ULL r; asm("mov.b64 %0, {%1,%2};" : "=l"(r) : "f"(x), "f"(y)); return r;
}
__device__ __forceinline__ void ffma2(ULL& acc, ULL a, ULL b) {
    asm volatile("fma.rn.f32x2 %0, %1, %2, %0;" : "+l"(acc) : "l"(a), "l"(b));
}
__device__ __forceinline__ float2 unpack2(ULL v) {
    float2 r; asm("mov.b64 {%0,%1}, %2;" : "=f"(r.x), "=f"(r.y) : "l"(v)); return r;
}
__device__ __forceinline__ float tanhf_fast(float x) {
    float r; asm("tanh.approx.f32 %0, %1;" : "=f"(r) : "f"(x)); return r;
}
__device__ __forceinline__ float sigf(float x) { return 0.5f * tanhf_fast(0.5f * x) + 0.5f; }
__device__ __forceinline__ void cp16s(unsigned int dst, const void* src) {
    asm volatile("cp.async.cg.shared.global [%0], [%1], 16;" :: "r"(dst), "l"(src));
}
__device__ __forceinline__ unsigned int smem_u32(const void* p) {
    return (unsigned int)__cvta_generic_to_shared(p);
}
__device__ __forceinline__ void ldm_x4(unsigned int& r0, unsigned int& r1,
                                       unsigned int& r2, unsigned int& r3,
                                       unsigned int addr) {
    asm volatile("ldmatrix.sync.aligned.m8n8.x4.shared.b16 {%0,%1,%2,%3}, [%4];"
                 : "=r"(r0), "=r"(r1), "=r"(r2), "=r"(r3) : "r"(addr));
}
__device__ __forceinline__ void mma16816(float* d, const unsigned int* a,
                                         const unsigned int* b) {
    asm volatile(
        "mma.sync.aligned.m16n8k16.row.col.f32.bf16.bf16.f32 "
        "{%0,%1,%2,%3}, {%4,%5,%6,%7}, {%8,%9}, {%0,%1,%2,%3};"
        : "+f"(d[0]), "+f"(d[1]), "+f"(d[2]), "+f"(d[3])
        : "r"(a[0]), "r"(a[1]), "r"(a[2]), "r"(a[3]), "r"(b[0]), "r"(b[1]));
}

// ---------------- device-global scratch ----------------------------------------
__device__ float d_bsum[NCG];
__device__ __nv_bfloat16 d_Xhi[(long)MROWS * KPX];    // embeddings [r=t*256+b][k]
__device__ __nv_bfloat16 d_Xlo[(long)MROWS * KPX];
__device__ __nv_bfloat16 d_Ghi[NCG * KPX];            // Wih [col][k]
__device__ __nv_bfloat16 d_Glo[NCG * KPX];
__device__ float d_gin[(long)MROWS * NCG];            // [r=t*256+b][col]
__device__ __nv_bfloat16 d_Ahi[(long)MROWS * KPAD];   // h2 [r=b*128+t][k]
__device__ __nv_bfloat16 d_Alo[(long)MROWS * KPAD];
__device__ __nv_bfloat16 d_Bhi[NCS * KPAD];           // W1 [col][k]
__device__ __nv_bfloat16 d_Blo[NCS * KPAD];
__device__ float d_S[(long)MROWS * NCS];              // [r=b*128+t][col]

// ---------------- init: embed gather + all weight prep (merged) ------------------
__global__ __launch_bounds__(512) void init_k(const int* __restrict__ x,
                                              const float* __restrict__ emb,
                                              const float* __restrict__ Wih_f,
                                              const float* __restrict__ Wih_b,
                                              const float* __restrict__ bih_f,
                                              const float* __restrict__ bhh_f,
                                              const float* __restrict__ bih_b,
                                              const float* __restrict__ bhh_b,
                                              const float* __restrict__ W1) {
    __shared__ int toks[128];
    const int tid = threadIdx.x;
    const int r0 = blockIdx.x * 128;

    // ---- xet part: one 128-row slab per block, k < 112 ----
    if (tid < 128) {
        int r = r0 + tid;
        toks[tid] = x[(r & 255) * TT + (r >> 8)];   // r = t*256+b
    }
    __syncthreads();
    for (int idx = tid; idx < 128 * 112; idx += 512) {
        int row = idx / 112, k = idx % 112;
        float v = (k < 100) ? emb[(long)toks[row] * EE + k] : 0.0f;
        __nv_bfloat16 hi = __float2bfloat16(v);
        long o = (long)(r0 + row) * KPX + k;
        d_Xhi[o] = hi;
        d_Xlo[o] = __float2bfloat16(v - __bfloat162float(hi));
    }

    // ---- prep part: grid-stride over weight transforms ----
    const int stride = gridDim.x * blockDim.x;
    const int i0 = blockIdx.x * blockDim.x + tid;
    for (int idx = i0; idx < NCG; idx += stride) {
        d_bsum[idx] = (idx < 400) ? (bih_f[idx] + bhh_f[idx])
                                  : (bih_b[idx - 400] + bhh_b[idx - 400]);
    }
    for (int idx = i0; idx < NCG * 112; idx += stride) {
        int col = idx / 112, k = idx % 112;
        float v = 0.0f;
        if (k < 100)
            v = (col < 400) ? Wih_f[col * 100 + k] : Wih_b[(col - 400) * 100 + k];
        __nv_bfloat16 hi = __float2bfloat16(v);
        d_Ghi[col * KPX + k] = hi;
        d_Glo[col * KPX + k] = __float2bfloat16(v - __bfloat162float(hi));
    }
    for (int idx = i0; idx < NCS * 208; idx += stride) {
        int col = idx / 208, k = idx % 208;
        float v = 0.0f;
        if (k < 200) {
            int s = col / MLPD, m = col % MLPD;
            v = W1[(s * 200 + k) * MLPD + m];
        }
        __nv_bfloat16 hi = __float2bfloat16(v);
        d_Bhi[col * KPAD + k] = hi;
        d_Blo[col * KPAD + k] = __float2bfloat16(v - __bfloat162float(hi));
    }
    for (int idx = i0; idx < MROWS * 8; idx += stride) {
        int r = idx >> 3, k = 200 + (idx & 7);
        d_Ahi[(long)r * KPAD + k] = __float2bfloat16(0.0f);
        d_Alo[(long)r * KPAD + k] = __float2bfloat16(0.0f);
    }
}

// ---------------- HMMA split-bf16 GEMM with 16-wide tail tile --------------------
// BM=128 BN=128, KFULL tiles of 32 + one 16 tail. 256 threads / 8 warps.
#define STC_SMEM (2 * 4 * 128 * 80)
template <int KFULL, int KS, bool BIAS>
__device__ __forceinline__ void tc_gemm(const __nv_bfloat16* __restrict__ Ahi,
                                        const __nv_bfloat16* __restrict__ Alo,
                                        const __nv_bfloat16* __restrict__ Bhi,
                                        const __nv_bfloat16* __restrict__ Blo,
                                        float* __restrict__ C, int NC,
                                        const float* __restrict__ bias) {
    extern __shared__ char smx[];
    const unsigned int tile = smem_u32(smx);
    const int tid = threadIdx.x;
    const int wid = tid >> 5;
    const int lane = tid & 31;
    const int wr = wid >> 1;
    const int wc = wid & 1;
    const int r0 = blockIdx.x * 128;
    const int cb = min((int)blockIdx.y * 128, NC - 128);

    float acc[2][8][4];
#pragma unroll
    for (int mt = 0; mt < 2; mt++)
#pragma unroll
        for (int nt = 0; nt < 8; nt++)
#pragma unroll
            for (int j = 0; j < 4; j++) acc[mt][nt][j] = 0.0f;

#define FILL_TILE(KC, BUF, NC4) do { \
    for (int u = tid; u < 128 * 4 * (NC4); u += 256) { \
        int arr = u / (128 * (NC4)); \
        int rem = u % (128 * (NC4)); \
        int row = rem / (NC4); \
        int c4 = rem % (NC4); \
        const __nv_bfloat16* src; \
        if (arr == 0)      src = &Ahi[(long)(r0 + row) * KS + (KC) + c4 * 8]; \
        else if (arr == 1) src = &Alo[(long)(r0 + row) * KS + (KC) + c4 * 8]; \
        else if (arr == 2) src = &Bhi[(long)(cb + row) * KS + (KC) + c4 * 8]; \
        else               src = &Blo[(long)(cb + row) * KS + (KC) + c4 * 8]; \
        cp16s(tile + (BUF) * 40960 + arr * 10240 + row * 80 + c4 * 16, src); \
    } \
    asm volatile("cp.async.commit_group;"); \
} while (0)

// one 16-wide k-step (ks selects which 16 cols of the staged tile)
#define MMA_STEP(KSI) do { \
    unsigned int ahi[2][4], alo[2][4]; \
    _Pragma("unroll") \
    for (int mt = 0; mt < 2; mt++) { \
        int row = wr * 32 + mt * 16 + (lane & 15); \
        unsigned int koff = ((lane >> 4) * 8 + (KSI) * 16) * 2; \
        ldm_x4(ahi[mt][0], ahi[mt][1], ahi[mt][2], ahi[mt][3], Ahib + row * 80 + koff); \
        ldm_x4(alo[mt][0], alo[mt][1], alo[mt][2], alo[mt][3], Alob + row * 80 + koff); \
    } \
    _Pragma("unroll") \
    for (int jn = 0; jn < 4; jn++) { \
        int nrow = wc * 64 + jn * 16 + ((lane >> 4) * 8) + (lane & 7); \
        unsigned int koff = ((KSI) * 16 + ((lane >> 3) & 1) * 8) * 2; \
        unsigned int bhi[4], blo[4]; \
        ldm_x4(bhi[0], bhi[1], bhi[2], bhi[3], Bhib + nrow * 80 + koff); \
        ldm_x4(blo[0], blo[1], blo[2], blo[3], Blob + nrow * 80 + koff); \
        _Pragma("unroll") \
        for (int half = 0; half < 2; half++) { \
            int nt = jn * 2 + half; \
            _Pragma("unroll") \
            for (int mt = 0; mt < 2; mt++) { \
                mma16816(acc[mt][nt], ahi[mt], bhi + half * 2); \
                mma16816(acc[mt][nt], ahi[mt], blo + half * 2); \
                mma16816(acc[mt][nt], alo[mt], bhi + half * 2); \
            } \
        } \
    } \
} while (0)

    FILL_TILE(0, 0, 4);

    for (int kt = 0; kt <= KFULL; kt++) {   // kt == KFULL is the 16-wide tail
        const int p = kt & 1;
        if (kt < KFULL) {
            if (kt + 1 == KFULL) FILL_TILE((kt + 1) * 32, p ^ 1, 2);
            else                 FILL_TILE((kt + 1) * 32, p ^ 1, 4);
            asm volatile("cp.async.wait_group 1;");
        } else {
            asm volatile("cp.async.wait_group 0;");
        }
        __syncthreads();

        const unsigned int bufb = tile + p * 40960;
        const unsigned int Ahib = bufb;
        const unsigned int Alob = bufb + 10240;
        const unsigned int Bhib = bufb + 20480;
        const unsigned int Blob = bufb + 30720;

        MMA_STEP(0);
        if (kt < KFULL) MMA_STEP(1);
        __syncthreads();
    }

#pragma unroll
    for (int mt = 0; mt < 2; mt++)
#pragma unroll
        for (int nt = 0; nt < 8; nt++) {
            int rg = r0 + wr * 32 + mt * 16 + (lane >> 2);
            int cg = cb + wc * 64 + nt * 8 + (lane & 3) * 2;
            float b0 = 0.f, b1 = 0.f;
            if (BIAS) { float2 bv = *(const float2*)&bias[cg]; b0 = bv.x; b1 = bv.y; }
            *(float2*)&C[(long)rg * NC + cg] =
                make_float2(acc[mt][nt][0] + b0, acc[mt][nt][1] + b1);
            *(float2*)&C[(long)(rg + 8) * NC + cg] =
                make_float2(acc[mt][nt][2] + b0, acc[mt][nt][3] + b1);
        }
#undef FILL_TILE
#undef MMA_STEP
}

__global__ __launch_bounds__(256, 2) void gates_tc_k() {
    tc_gemm<3, KPX, true>(d_Xhi, d_Xlo, d_Ghi, d_Glo, d_gin, NCG, d_bsum);   // K = 112
}
__global__ __launch_bounds__(256, 2) void s_tc_k() {
    tc_gemm<6, KPAD, false>(d_Ahi, d_Alo, d_Bhi, d_Blo, d_S, NCS, nullptr);  // K = 208
}

// ---------------- LSTM recurrence (R12-proven loop; bf16 hi/lo h output) ---------
__global__ __launch_bounds__(800, 1) void lstm_k(const float* __restrict__ Whh_f,
                                                 const float* __restrict__ Whh_b) {
    __shared__ __align__(16) float hs[2][4 * 116];
    const int tid = threadIdx.x;
    const int dir = blockIdx.x >> 6;
    const int b0 = (blockIdx.x & 63) * 4;
    const float* __restrict__ Whh = dir ? Whh_b : Whh_f;

    const int hid = tid >> 3;
    const int sub = tid & 7;
    const int q = sub >> 1;
    const int gh = sub & 1;
    const int hi2 = (q >> 1) & 1;
    const int lo = q & 1;

    ULL w[2][13];
#pragma unroll
    for (int g2 = 0; g2 < 2; g2++) {
        const float* row = Whh + ((gh * 2 + g2) * 100 + hid) * 100 + q * 25;
#pragma unroll
        for (int p = 0; p < 12; p++) w[g2][p] = pack2(row[2 * p], row[2 * p + 1]);
        w[g2][12] = pack2(row[24], 0.0f);
    }
    for (int idx = tid; idx < 2 * 4 * 116; idx += 800) hs[0][idx] = 0.0f;

    const int hq = hid / 25, hr = hid % 25;
    float c = 0.0f;
    float g0, g1;
    {
        int t0 = dir ? (TT - 1) : 0;
        const float* gp = &d_gin[((long)(t0 * 256 + b0 + q)) * NCG + dir * 400 + gh * 200 + hid];
        g0 = gp[0]; g1 = gp[100];
    }
    __syncthreads();

    for (int step = 0; step < TT; ++step) {
        const int t = dir ? (TT - 1 - step) : step;
        const float* hbuf = hs[step & 1];
        float* hnxt = hs[(step + 1) & 1];

        float v[4][2];
#pragma unroll
        for (int b = 0; b < 4; b++) {
            const float* hb = &hbuf[b * 116 + q * 28];
            ULL a0 = 0ull, a1 = 0ull;
#pragma unroll
            for (int m = 0; m < 6; m++) {
                ulonglong2 hp = *(const ulonglong2*)(hb + 4 * m);
                ffma2(a0, w[0][2 * m], hp.x); ffma2(a0, w[0][2 * m + 1], hp.y);
                ffma2(a1, w[1][2 * m], hp.x); ffma2(a1, w[1][2 * m + 1], hp.y);
            }
            {
                ULL ht = *(const ULL*)(hb + 24);
                ffma2(a0, w[0][12], ht); ffma2(a1, w[1][12], ht);
            }
            float2 f0 = unpack2(a0), f1 = unpack2(a1);
            v[b][0] = f0.x + f0.y;
            v[b][1] = f1.x + f1.y;
        }

        float u[2][2];
#pragma unroll
        for (int j = 0; j < 2; j++)
#pragma unroll
            for (int g = 0; g < 2; g++) {
                float keep = hi2 ? v[2 + j][g] : v[j][g];
                float send = hi2 ? v[j][g]     : v[2 + j][g];
                u[j][g] = keep + __shfl_xor_sync(0xFFFFFFFFu, send, 4);
            }
        float s0, s1;
        {
            float k0 = lo ? u[1][0] : u[0][0];
            float e0 = lo ? u[0][0] : u[1][0];
            s0 = k0 + __shfl_xor_sync(0xFFFFFFFFu, e0, 2);
            float k1 = lo ? u[1][1] : u[0][1];
            float e1 = lo ? u[0][1] : u[1][1];
            s1 = k1 + __shfl_xor_sync(0xFFFFFFFFu, e1, 2);
        }

        float uA = g0 + s0;
        float uB = g1 + s1;
        float oA = __shfl_xor_sync(0xFFFFFFFFu, uA, 1);
        float oB = __shfl_xor_sync(0xFFFFFFFFu, uB, 1);
        float pi = gh ? oA : uA;
        float pf = gh ? oB : uB;
        float pg = gh ? uA : oA;
        float po = gh ? uB : oB;
        c = sigf(pf) * c + sigf(pi) * tanhf_fast(pg);
        float h = sigf(po) * tanhf_fast(c);
        if (gh == 0) {
            hnxt[q * 116 + hq * 28 + hr] = h;
            long r = (long)(b0 + q) * TT + t;
            __nv_bfloat16 bh = __float2bfloat16(h);
            __nv_bfloat16 bl = __float2bfloat16(h - __bfloat162float(bh));
            d_Ahi[r * KPAD + dir * 100 + hid] = bh;
            d_Alo[r * KPAD + dir * 100 + hid] = bl;
        }
        {
            int sn = (step + 1 < TT) ? (step + 1) : step;
            int tn = dir ? (TT - 1 - sn) : sn;
            const float* gp = &d_gin[((long)(tn * 256 + b0 + q)) * NCG + dir * 400 + gh * 200 + hid];
            g0 = gp[0]; g1 = gp[100];
        }
        __syncthreads();
    }
}

// ---------------- combine: smem-staged weights + gather + tanh + softmax ---------
__global__ __launch_bounds__(256) void combine_k(const int* __restrict__ paths,
                                                 const float* __restrict__ b1,
                                                 const float* __restrict__ W2,
                                                 const float* __restrict__ b2,
                                                 float* __restrict__ out) {
    __shared__ float sb1[MLPD];
    __shared__ float sW2[MLPD * 3];
    __shared__ float sb2[3];
    const int tid = threadIdx.x;
    for (int i = tid; i < MLPD; i += 256) sb1[i] = b1[i];
    for (int i = tid; i < MLPD * 3; i += 256) sW2[i] = W2[i];
    if (tid < 3) sb2[tid] = b2[tid];
    __syncthreads();

    const int warp = (blockIdx.x * blockDim.x + tid) >> 5;
    const int lane = tid & 31;
    if (warp >= BB * CC) return;
    const int b = warp / CC;

    const int* p = &paths[warp * 3];
    int p0 = __ldg(p), p1 = __ldg(p + 1), p2 = __ldg(p + 2);
    int i0 = min(max(p0, 0), TT - 1);
    int i1 = min(max(p1, 0), TT - 1);
    int i2 = min(max(p2, 0), TT - 1);

    const float* S0 = &d_S[(long)(b * TT + i0) * NCS];
    const float* S1 = &d_S[(long)(b * TT + i1) * NCS + 300];
    const float* S2 = &d_S[(long)(b * TT + i2) * NCS + 600];

    float z0 = 0.f, z1 = 0.f, z2 = 0.f;
    for (int m = lane; m < MLPD; m += 32) {
        float hv = sb1[m];
        if (p0 >= 0) hv += S0[m];
        if (p1 >= 0) hv += S1[m];
        if (p2 >= 0) hv += S2[m];
        hv = tanhf_fast(hv);
        z0 = fmaf(hv, sW2[m * 3 + 0], z0);
        z1 = fmaf(hv, sW2[m * 3 + 1], z1);
        z2 = fmaf(hv, sW2[m * 3 + 2], z2);
    }
#pragma unroll
    for (int off = 16; off; off >>= 1) {
        z0 += __shfl_xor_sync(0xFFFFFFFFu, z0, off);
        z1 += __shfl_xor_sync(0xFFFFFFFFu, z1, off);
        z2 += __shfl_xor_sync(0xFFFFFFFFu, z2, off);
    }
    if (lane == 0) {
        z0 += sb2[0]; z1 += sb2[1]; z2 += sb2[2];
        float mx = fmaxf(z0, fmaxf(z1, z2));
        float e0 = __expf(z0 - mx), e1 = __expf(z1 - mx), e2 = __expf(z2 - mx);
        float inv = 1.0f / (e0 + e1 + e2);
        out[warp * 3 + 0] = e0 * inv;
        out[warp * 3 + 1] = e1 * inv;
        out[warp * 3 + 2] = e2 * inv;
    }
}

// -------------------------------- launch -----------------------------------------
extern "C" void kernel_launch(void* const* d_in, const int* in_sizes, int n_in,
                              void* d_out, int out_size) {
    const int*   x     = (const int*)  d_in[0];
    const int*   paths = (const int*)  d_in[1];
    const float* emb   = (const float*)d_in[2];
    const float* Whh_f = (const float*)d_in[4];
    const float* Whh_b = (const float*)d_in[8];
    const float* W1    = (const float*)d_in[11];
    const float* b1    = (const float*)d_in[12];
    const float* W2    = (const float*)d_in[13];
    const float* b2    = (const float*)d_in[14];
    float* out = (float*)d_out;

    cudaFuncSetAttribute(gates_tc_k, cudaFuncAttributeMaxDynamicSharedMemorySize, STC_SMEM);
    cudaFuncSetAttribute(s_tc_k, cudaFuncAttributeMaxDynamicSharedMemorySize, STC_SMEM);

    init_k<<<256, 512>>>(x, emb,
                         (const float*)d_in[3], (const float*)d_in[7],
                         (const float*)d_in[5], (const float*)d_in[6],
                         (const float*)d_in[9], (const float*)d_in[10], W1);

    { dim3 g(256, 7); gates_tc_k<<<g, 256, STC_SMEM>>>(); }   // HMMA gates GEMM, K=112

    lstm_k<<<128, 800>>>(Whh_f, Whh_b);

    { dim3 g(256, 8); s_tc_k<<<g, 256, STC_SMEM>>>(); }       // HMMA S GEMM, K=208

    {
        int warps = BB * CC;
        int blocks = (warps * 32 + 255) / 256;
        combine_k<<<blocks, 256>>>(paths, b1, W2, b2, out);
    }
}